// round 13
// baseline (speedup 1.0000x reference)
#include <cuda_runtime.h>

#define BB 32
#define CC 256
#define LL 64
#define NHKD 16
#define QKV_CH 48

// scratch (device globals; no allocations)
__device__ __align__(16) float g_xh[BB*CC*LL];        // mean over W : [b][c][h]
__device__ __align__(16) float g_xw[BB*CC*LL];        // mean over H : [b][c][w]
__device__ __align__(16) float g_P[BB*CC*LL];         // (A*fs+fsh)*g*0.1
__device__ __align__(16) float g_Q[BB*CC*LL];         // (B*fs)*g*0.1

// ---------------------------------------------------------------------------
// K1: 4 tiles per block (grid 2048), double-buffered row-transpose so the
// per-tile reduce tail overlaps the next tile's streaming loads.
// ---------------------------------------------------------------------------
__global__ void k1_reduce(const float* __restrict__ x) {
    int t = threadIdx.x;                       // 256 threads
    __shared__ float scol[4][64];
    __shared__ float srow[2][64][17];          // padded: conflict-free
    scol[t >> 6][t & 63] = 0.f;                // zero all 4 tile buffers
    __syncthreads();

    #pragma unroll
    for (int tile = 0; tile < 4; ++tile) {
        int bc = blockIdx.x * 4 + tile;        // b*256+c
        const float4* xt = (const float4*)(x + (size_t)bc * 4096);
        int buf = tile & 1;

        float c0 = 0.f, c1 = 0.f, c2 = 0.f, c3 = 0.f;
        #pragma unroll
        for (int i = 0; i < 4; ++i) {
            int j = t + 256 * i;               // float4 index in [0,1024)
            float4 v = xt[j];
            srow[buf][j >> 4][t & 15] = v.x + v.y + v.z + v.w;
            c0 += v.x; c1 += v.y; c2 += v.z; c3 += v.w;
        }
        c0 += __shfl_xor_sync(0xffffffffu, c0, 16);
        c1 += __shfl_xor_sync(0xffffffffu, c1, 16);
        c2 += __shfl_xor_sync(0xffffffffu, c2, 16);
        c3 += __shfl_xor_sync(0xffffffffu, c3, 16);
        if ((t & 31) < 16) {
            int cb = (t & 15) * 4;
            atomicAdd(&scol[tile][cb + 0], c0);
            atomicAdd(&scol[tile][cb + 1], c1);
            atomicAdd(&scol[tile][cb + 2], c2);
            atomicAdd(&scol[tile][cb + 3], c3);
        }
        __syncthreads();
        if (t < 64) {
            float s = 0.f;
            #pragma unroll
            for (int c = 0; c < 16; ++c) s += srow[buf][t][c];
            g_xh[bc * 64 + t] = s * (1.f / 64.f);
            g_xw[bc * 64 + t] = scol[tile][t] * (1.f / 64.f);
        }
        // no extra sync: next tile writes srow[buf^1]; srow[buf] is reused
        // only after the NEXT __syncthreads, by which reducers have passed.
    }
}

// ---------------------------------------------------------------------------
// K2345: qkv projection + axial attention + SE gate + P/Q, fused via a
// 2-CTA cluster; cross-axis means exchanged through DSMEM.
// 64 blocks (b*2+axis), 256 threads.
// ---------------------------------------------------------------------------
__global__ void __cluster_dims__(2, 1, 1)
k2345_fused(const float* __restrict__ w_qkv,
            const float* __restrict__ qs,
            const float* __restrict__ qsh,
            const float* __restrict__ pos_h,
            const float* __restrict__ pos_w,
            const float* __restrict__ w_fusion,
            const float* __restrict__ fs,
            const float* __restrict__ fsh,
            const float* __restrict__ wg1,
            const float* __restrict__ g1s,
            const float* __restrict__ g1sh,
            const float* __restrict__ wg2,
            const float* __restrict__ g2s,
            const float* __restrict__ g2sh) {
    int blk  = blockIdx.x;         // b*2+axis in [0,64); cluster = {2b, 2b+1}
    int axis = blk & 1;            // == cluster ctarank
    int b    = blk >> 1;
    const float* xm = (axis == 0 ? g_xh : g_xw) + b * CC * 64;

    __shared__ __align__(16) float swT[64][QKV_CH];  // 12 KB [cl][o]
    __shared__ float sx[64][64];                     // 16 KB [c_local][l]
    __shared__ float sT[64][53];                     // 13.3 KB qkv^T [l][o]
    __shared__ __align__(16) float sM[NHKD][64];     // 4 KB attention out
    __shared__ float smeans[32];                     // both axes' means
    __shared__ float y[256];
    __shared__ float t1[64];

    int t  = threadIdx.x;
    int l  = t & 63;
    int og = t >> 6;                   // 4 o-groups of 12
    int lane = t & 31, wrp = t >> 5;

    // ---------------- phase A: qkv projection ----------------
    float acc[12];
    #pragma unroll
    for (int j = 0; j < 12; ++j) acc[j] = 0.f;

    for (int cc = 0; cc < 256; cc += 64) {
        for (int e = t; e < QKV_CH * 64; e += 256) {
            int o = e >> 6, cl = e & 63;
            swT[cl][o] = w_qkv[o * 256 + cc + cl];
        }
        for (int e = t; e < 64 * 64; e += 256) {
            int cl = e >> 6, ll = e & 63;
            sx[cl][ll] = xm[(cc + cl) * 64 + ll];
        }
        __syncthreads();
        const float4* swT4 = (const float4*)swT;     // 12 float4 per row
        #pragma unroll 4
        for (int cl = 0; cl < 64; ++cl) {
            float xv = sx[cl][l];
            float4 w0 = swT4[cl * 12 + og * 3 + 0];  // warp-uniform broadcast
            float4 w1 = swT4[cl * 12 + og * 3 + 1];
            float4 w2 = swT4[cl * 12 + og * 3 + 2];
            acc[0] += w0.x * xv; acc[1]  += w0.y * xv;
            acc[2] += w0.z * xv; acc[3]  += w0.w * xv;
            acc[4] += w1.x * xv; acc[5]  += w1.y * xv;
            acc[6] += w1.z * xv; acc[7]  += w1.w * xv;
            acc[8] += w2.x * xv; acc[9]  += w2.y * xv;
            acc[10]+= w2.z * xv; acc[11] += w2.w * xv;
        }
        __syncthreads();
    }

    const float* pos = axis ? pos_w : pos_h;
    #pragma unroll
    for (int j = 0; j < 12; ++j) {
        int o = og * 12 + j;
        float v = acc[j] * qs[o] + qsh[o];
        if (o < 32) v += pos[(o & 15) * 64 + l];   // pos added to q and k
        sT[l][o] = v;
    }
    __syncthreads();

    // ---------------- phase B: attention (threads 0..127) ----------------
    if (t < 128) {
        int i  = t & 63;
        int qo = (t >> 6) * 8;

        float qreg[8];
        #pragma unroll
        for (int d = 0; d < 8; ++d) qreg[d] = sT[i][qo + d];

        float a[64];
        float m = -1e30f;
        #pragma unroll
        for (int j = 0; j < 64; ++j) {
            float s = 0.f;
            #pragma unroll
            for (int d = 0; d < 8; ++d) s += qreg[d] * sT[j][16 + qo + d];
            s *= 0.35355339059327373f;  // 8^-0.5
            a[j] = s;
            m = fmaxf(m, s);
        }
        float ssum = 0.f;
        #pragma unroll
        for (int j = 0; j < 64; ++j) {
            float e = __expf(a[j] - m);
            a[j] = e;
            ssum += e;
        }
        float inv = 1.f / ssum;

        float acc2[8] = {0.f, 0.f, 0.f, 0.f, 0.f, 0.f, 0.f, 0.f};
        #pragma unroll
        for (int j = 0; j < 64; ++j) {
            float aj = a[j];
            #pragma unroll
            for (int d = 0; d < 8; ++d) acc2[d] += aj * sT[j][32 + qo + d];
        }
        #pragma unroll
        for (int d = 0; d < 8; ++d) sM[qo + d][i] = acc2[d] * inv;
    }
    __syncthreads();

    // ---- prefetch this thread's w_fusion row (overlaps barrier wait) ----
    float4 wf[8];
    {
        const float4* wr = (const float4*)(w_fusion + t * 32);
        #pragma unroll
        for (int i = 0; i < 8; ++i) wf[i] = wr[i];
    }

    // ---------------- phase C: channel means + DSMEM exchange ----------------
    {
        int ch = t >> 4, sub = t & 15;          // 16 ch x 16 threads
        float s = 0.f;
        #pragma unroll
        for (int k = 0; k < 4; ++k) s += sM[ch][sub + 16 * k];
        #pragma unroll
        for (int off = 8; off >= 1; off >>= 1)
            s += __shfl_xor_sync(0xffffffffu, s, off);
        if (sub == 0) {
            float mv = s * (1.f / 64.f);
            int slot = axis * 16 + ch;
            smeans[slot] = mv;                  // local copy
            // remote copy into the peer CTA's smeans[slot]
            unsigned la = (unsigned)__cvta_generic_to_shared(&smeans[slot]);
            unsigned ra, peer = axis ^ 1;
            asm("mapa.shared::cluster.u32 %0, %1, %2;"
                : "=r"(ra) : "r"(la), "r"(peer));
            asm volatile("st.shared::cluster.f32 [%0], %1;"
                         :: "r"(ra), "f"(mv) : "memory");
        }
    }
    // cluster barrier: release own mean-store, acquire peer's
    asm volatile("barrier.cluster.arrive.aligned;" ::: "memory");
    asm volatile("barrier.cluster.wait.aligned;"   ::: "memory");

    // ---------------- phase D: gate chain (duplicated per CTA) ----------------
    {
        float s = 0.f;
        #pragma unroll
        for (int c4 = 0; c4 < 8; ++c4) {
            float4 wv = wf[c4];
            s += wv.x * smeans[c4 * 4 + 0] + wv.y * smeans[c4 * 4 + 1]
               + wv.z * smeans[c4 * 4 + 2] + wv.w * smeans[c4 * 4 + 3];
        }
        y[t] = s * fs[t] + fsh[t];
    }
    __syncthreads();

    // stage 3: t1 = silu(cbn(wg1 @ y)) — warp-per-row, coalesced lanes
    #pragma unroll
    for (int o = wrp; o < 64; o += 8) {
        const float* r = wg1 + o * 256;
        float s = 0.f;
        #pragma unroll
        for (int i = 0; i < 8; ++i) {
            int c = lane + 32 * i;
            s += r[c] * y[c];
        }
        #pragma unroll
        for (int off = 16; off >= 1; off >>= 1)
            s += __shfl_xor_sync(0xffffffffu, s, off);
        if (lane == 0) {
            s = s * g1s[o] + g1sh[o];
            t1[o] = s / (1.f + __expf(-s));
        }
    }
    __syncthreads();

    // stage 4: gate = sigmoid(cbn(wg2 @ t1))
    float gate;
    {
        const float4* wr = (const float4*)(wg2 + t * 64);
        float s = 0.f;
        #pragma unroll
        for (int c4 = 0; c4 < 16; ++c4) {
            float4 wv = wr[c4];
            s += wv.x * t1[c4 * 4 + 0] + wv.y * t1[c4 * 4 + 1]
               + wv.z * t1[c4 * 4 + 2] + wv.w * t1[c4 * 4 + 3];
        }
        s = s * g2s[t] + g2sh[t];
        gate = 1.f / (1.f + __expf(-s));
    }

    // ---------------- phase E: this axis' P or Q row for o = t ----------------
    int o = t;
    float scale = fs[o] * gate * 0.1f;
    float bias  = axis ? 0.f : fsh[o] * gate * 0.1f;
    float w[16];
    const float* wff = (const float*)wf;
    if (axis == 0) {
        #pragma unroll
        for (int c = 0; c < 16; ++c) w[c] = wff[c];
    } else {
        #pragma unroll
        for (int c = 0; c < 16; ++c) w[c] = wff[16 + c];
    }
    float* dst = (axis ? g_Q : g_P) + (b * 256 + o) * 64;
    const float4* base = (const float4*)sM;        // sM == this axis' attention

    #pragma unroll
    for (int lg = 0; lg < 16; ++lg) {
        float4 acc2 = {0.f, 0.f, 0.f, 0.f};
        #pragma unroll
        for (int c = 0; c < 16; ++c) {
            float4 xv = base[c * 16 + lg];     // warp-uniform broadcast
            acc2.x += w[c] * xv.x; acc2.y += w[c] * xv.y;
            acc2.z += w[c] * xv.z; acc2.w += w[c] * xv.w;
        }
        float4 r;
        r.x = acc2.x * scale + bias; r.y = acc2.y * scale + bias;
        r.z = acc2.z * scale + bias; r.w = acc2.w * scale + bias;
        ((float4*)dst)[lg] = r;
    }
}

// ---------------------------------------------------------------------------
// K6: 4 tiles per block (grid 2048), descending order (R10 L2 win preserved),
// double-buffered P/Q with next-tile prefetch hidden under streaming.
// __stcs on stores only (R12 win).
// ---------------------------------------------------------------------------
__global__ void k6_final(const float* __restrict__ x, float* __restrict__ out) {
    int base = (2047 - blockIdx.x) * 4;    // tiles base+3 .. base+0, descending
    __shared__ float  sp[2][64];
    __shared__ float4 sq4[2][16];
    int t = threadIdx.x;

    // prefetch first tile (base+3) into buffer 0
    if (t < 64) sp[0][t] = g_P[(base + 3) * 64 + t];
    else if (t < 80) sq4[0][t - 64] = ((const float4*)(g_Q + (base + 3) * 64))[t - 64];

    #pragma unroll
    for (int k = 0; k < 4; ++k) {
        __syncthreads();                   // prefetched buf ready; prev reads done
        int blk = base + 3 - k;
        int buf = k & 1;
        if (k < 3) {                       // prefetch next tile into other buffer
            int nb = blk - 1;
            if (t < 64) sp[buf ^ 1][t] = g_P[nb * 64 + t];
            else if (t < 80) sq4[buf ^ 1][t - 64] =
                ((const float4*)(g_Q + nb * 64))[t - 64];
        }
        const float4* xi = (const float4*)(x + (size_t)blk * 4096);
        float4*       xo = (float4*)(out + (size_t)blk * 4096);
        #pragma unroll
        for (int i = 0; i < 4; ++i) {
            int j = t + 256 * i;
            float  p  = sp[buf][j >> 4];
            float4 qv = sq4[buf][j & 15];
            float4 xv = xi[j];
            float4 r;
            r.x = xv.x + p + qv.x;
            r.y = xv.y + p + qv.y;
            r.z = xv.z + p + qv.z;
            r.w = xv.w + p + qv.w;
            __stcs(xo + j, r);
        }
    }
}

// ---------------------------------------------------------------------------
// Input identification by element count (robust to metadata ordering).
// ---------------------------------------------------------------------------
extern "C" void kernel_launch(void* const* d_in, const int* in_sizes, int n_in,
                              void* d_out, int out_size) {
    const float *x = 0, *w_qkv = 0, *qkv_scale = 0, *qkv_shift = 0;
    const float *pos_h = 0, *pos_w = 0, *w_fusion = 0;
    const float *fusion_scale = 0, *fusion_shift = 0;
    const float *w_g1 = 0, *g1_scale = 0, *g1_shift = 0;
    const float *w_g2 = 0, *g2_scale = 0, *g2_shift = 0;

    int n48 = 0, n64 = 0, n256 = 0, n1024 = 0, n16384 = 0;
    for (int i = 0; i < n_in; ++i) {
        const float* p = (const float*)d_in[i];
        switch (in_sizes[i]) {
            case 33554432: x = p; break;
            case 12288:    w_qkv = p; break;
            case 8192:     w_fusion = p; break;
            case 48:
                if (n48++ == 0) qkv_scale = p; else qkv_shift = p; break;
            case 1024:
                if (n1024++ == 0) pos_h = p; else pos_w = p; break;
            case 16384:
                if (n16384++ == 0) w_g1 = p; else w_g2 = p; break;
            case 64:
                if (n64++ == 0) g1_scale = p; else g1_shift = p; break;
            case 256:
                switch (n256++) {
                    case 0: fusion_scale = p; break;
                    case 1: fusion_shift = p; break;
                    case 2: g2_scale = p; break;
                    default: g2_shift = p; break;
                }
                break;
            default: break;
        }
    }
    float* out = (float*)d_out;

    k1_reduce<<<2048, 256>>>(x);
    k2345_fused<<<64, 256>>>(w_qkv, qkv_scale, qkv_shift, pos_h, pos_w,
                             w_fusion, fusion_scale, fusion_shift,
                             w_g1, g1_scale, g1_shift,
                             w_g2, g2_scale, g2_shift);
    k6_final<<<2048, 256>>>(x, out);
}

// round 14
// speedup vs baseline: 1.0764x; 1.0764x over previous
#include <cuda_runtime.h>

#define BB 32
#define CC 256
#define LL 64
#define NHKD 16
#define QKV_CH 48

// scratch (device globals; no allocations)
__device__ __align__(16) float g_xh[BB*CC*LL];        // mean over W : [b][c][h]
__device__ __align__(16) float g_xw[BB*CC*LL];        // mean over H : [b][c][w]
__device__ __align__(16) float g_P[BB*CC*LL];         // (A*fs+fsh)*g*0.1
__device__ __align__(16) float g_Q[BB*CC*LL];         // (B*fs)*g*0.1

// ---------------------------------------------------------------------------
// K1: per-(b,c) 64x64 tile -> row + col means. 8192 blocks (R12 occupancy).
// Pure smem reduction: no shfl chains, no atomics in the hot path —
// 4 LDG.128 + 5 STS + FADDs per thread, then a 64-thread gather tail.
// ---------------------------------------------------------------------------
__global__ void k1_reduce(const float* __restrict__ x) {
    int bc = blockIdx.x;                       // b*256 + c
    const float4* xt = (const float4*)(x + (size_t)bc * 4096);
    int t = threadIdx.x;                       // 256 threads
    __shared__ float srow[64][17];             // row partials, padded
    __shared__ __align__(16) float4 scolp[16][17];  // col partials, padded

    float c0 = 0.f, c1 = 0.f, c2 = 0.f, c3 = 0.f;
    #pragma unroll
    for (int i = 0; i < 4; ++i) {
        int j = t + 256 * i;                   // float4 index in [0,1024)
        float4 v = xt[j];
        srow[j >> 4][t & 15] = v.x + v.y + v.z + v.w;  // row partial
        c0 += v.x; c1 += v.y; c2 += v.z; c3 += v.w;    // col partials
    }
    scolp[t >> 4][t & 15] = make_float4(c0, c1, c2, c3);
    __syncthreads();

    if (t < 64) {
        float s = 0.f;
        #pragma unroll
        for (int c = 0; c < 16; ++c) s += srow[t][c];
        g_xh[bc * 64 + t] = s * (1.f / 64.f);

        // column t lives at float offset r*68 + t (rows of 17 float4 = 68 f)
        const float* scf = (const float*)scolp;
        float sc = 0.f;
        #pragma unroll
        for (int r = 0; r < 16; ++r) sc += scf[r * 68 + t];
        g_xw[bc * 64 + t] = sc * (1.f / 64.f);
    }
}

// ---------------------------------------------------------------------------
// K2345: qkv projection + axial attention + SE gate + P/Q, fused via a
// 2-CTA cluster; cross-axis means exchanged through DSMEM.
// 64 blocks (b*2+axis), 256 threads. (R11/R12 form — pinned.)
// ---------------------------------------------------------------------------
__global__ void __cluster_dims__(2, 1, 1)
k2345_fused(const float* __restrict__ w_qkv,
            const float* __restrict__ qs,
            const float* __restrict__ qsh,
            const float* __restrict__ pos_h,
            const float* __restrict__ pos_w,
            const float* __restrict__ w_fusion,
            const float* __restrict__ fs,
            const float* __restrict__ fsh,
            const float* __restrict__ wg1,
            const float* __restrict__ g1s,
            const float* __restrict__ g1sh,
            const float* __restrict__ wg2,
            const float* __restrict__ g2s,
            const float* __restrict__ g2sh) {
    int blk  = blockIdx.x;         // b*2+axis in [0,64); cluster = {2b, 2b+1}
    int axis = blk & 1;            // == cluster ctarank
    int b    = blk >> 1;
    const float* xm = (axis == 0 ? g_xh : g_xw) + b * CC * 64;

    __shared__ __align__(16) float swT[64][QKV_CH];  // 12 KB [cl][o]
    __shared__ float sx[64][64];                     // 16 KB [c_local][l]
    __shared__ float sT[64][53];                     // 13.3 KB qkv^T [l][o]
    __shared__ __align__(16) float sM[NHKD][64];     // 4 KB attention out
    __shared__ float smeans[32];                     // both axes' means
    __shared__ float y[256];
    __shared__ float t1[64];

    int t  = threadIdx.x;
    int l  = t & 63;
    int og = t >> 6;                   // 4 o-groups of 12
    int lane = t & 31, wrp = t >> 5;

    // ---------------- phase A: qkv projection ----------------
    float acc[12];
    #pragma unroll
    for (int j = 0; j < 12; ++j) acc[j] = 0.f;

    for (int cc = 0; cc < 256; cc += 64) {
        for (int e = t; e < QKV_CH * 64; e += 256) {
            int o = e >> 6, cl = e & 63;
            swT[cl][o] = w_qkv[o * 256 + cc + cl];
        }
        for (int e = t; e < 64 * 64; e += 256) {
            int cl = e >> 6, ll = e & 63;
            sx[cl][ll] = xm[(cc + cl) * 64 + ll];
        }
        __syncthreads();
        const float4* swT4 = (const float4*)swT;     // 12 float4 per row
        #pragma unroll 4
        for (int cl = 0; cl < 64; ++cl) {
            float xv = sx[cl][l];
            float4 w0 = swT4[cl * 12 + og * 3 + 0];  // warp-uniform broadcast
            float4 w1 = swT4[cl * 12 + og * 3 + 1];
            float4 w2 = swT4[cl * 12 + og * 3 + 2];
            acc[0] += w0.x * xv; acc[1]  += w0.y * xv;
            acc[2] += w0.z * xv; acc[3]  += w0.w * xv;
            acc[4] += w1.x * xv; acc[5]  += w1.y * xv;
            acc[6] += w1.z * xv; acc[7]  += w1.w * xv;
            acc[8] += w2.x * xv; acc[9]  += w2.y * xv;
            acc[10]+= w2.z * xv; acc[11] += w2.w * xv;
        }
        __syncthreads();
    }

    const float* pos = axis ? pos_w : pos_h;
    #pragma unroll
    for (int j = 0; j < 12; ++j) {
        int o = og * 12 + j;
        float v = acc[j] * qs[o] + qsh[o];
        if (o < 32) v += pos[(o & 15) * 64 + l];   // pos added to q and k
        sT[l][o] = v;
    }
    __syncthreads();

    // ---------------- phase B: attention (threads 0..127) ----------------
    if (t < 128) {
        int i  = t & 63;
        int qo = (t >> 6) * 8;

        float qreg[8];
        #pragma unroll
        for (int d = 0; d < 8; ++d) qreg[d] = sT[i][qo + d];

        float a[64];
        float m = -1e30f;
        #pragma unroll
        for (int j = 0; j < 64; ++j) {
            float s = 0.f;
            #pragma unroll
            for (int d = 0; d < 8; ++d) s += qreg[d] * sT[j][16 + qo + d];
            s *= 0.35355339059327373f;  // 8^-0.5
            a[j] = s;
            m = fmaxf(m, s);
        }
        float ssum = 0.f;
        #pragma unroll
        for (int j = 0; j < 64; ++j) {
            float e = __expf(a[j] - m);
            a[j] = e;
            ssum += e;
        }
        float inv = 1.f / ssum;

        float acc2[8] = {0.f, 0.f, 0.f, 0.f, 0.f, 0.f, 0.f, 0.f};
        #pragma unroll
        for (int j = 0; j < 64; ++j) {
            float aj = a[j];
            #pragma unroll
            for (int d = 0; d < 8; ++d) acc2[d] += aj * sT[j][32 + qo + d];
        }
        #pragma unroll
        for (int d = 0; d < 8; ++d) sM[qo + d][i] = acc2[d] * inv;
    }
    __syncthreads();

    // ---- prefetch this thread's w_fusion row (overlaps barrier wait) ----
    float4 wf[8];
    {
        const float4* wr = (const float4*)(w_fusion + t * 32);
        #pragma unroll
        for (int i = 0; i < 8; ++i) wf[i] = wr[i];
    }

    // ---------------- phase C: channel means + DSMEM exchange ----------------
    {
        int ch = t >> 4, sub = t & 15;          // 16 ch x 16 threads
        float s = 0.f;
        #pragma unroll
        for (int k = 0; k < 4; ++k) s += sM[ch][sub + 16 * k];
        #pragma unroll
        for (int off = 8; off >= 1; off >>= 1)
            s += __shfl_xor_sync(0xffffffffu, s, off);
        if (sub == 0) {
            float mv = s * (1.f / 64.f);
            int slot = axis * 16 + ch;
            smeans[slot] = mv;                  // local copy
            // remote copy into the peer CTA's smeans[slot]
            unsigned la = (unsigned)__cvta_generic_to_shared(&smeans[slot]);
            unsigned ra, peer = axis ^ 1;
            asm("mapa.shared::cluster.u32 %0, %1, %2;"
                : "=r"(ra) : "r"(la), "r"(peer));
            asm volatile("st.shared::cluster.f32 [%0], %1;"
                         :: "r"(ra), "f"(mv) : "memory");
        }
    }
    // cluster barrier: release own mean-store, acquire peer's
    asm volatile("barrier.cluster.arrive.aligned;" ::: "memory");
    asm volatile("barrier.cluster.wait.aligned;"   ::: "memory");

    // ---------------- phase D: gate chain (duplicated per CTA) ----------------
    {
        float s = 0.f;
        #pragma unroll
        for (int c4 = 0; c4 < 8; ++c4) {
            float4 wv = wf[c4];
            s += wv.x * smeans[c4 * 4 + 0] + wv.y * smeans[c4 * 4 + 1]
               + wv.z * smeans[c4 * 4 + 2] + wv.w * smeans[c4 * 4 + 3];
        }
        y[t] = s * fs[t] + fsh[t];
    }
    __syncthreads();

    // stage 3: t1 = silu(cbn(wg1 @ y)) — warp-per-row, coalesced lanes
    #pragma unroll
    for (int o = wrp; o < 64; o += 8) {
        const float* r = wg1 + o * 256;
        float s = 0.f;
        #pragma unroll
        for (int i = 0; i < 8; ++i) {
            int c = lane + 32 * i;
            s += r[c] * y[c];
        }
        #pragma unroll
        for (int off = 16; off >= 1; off >>= 1)
            s += __shfl_xor_sync(0xffffffffu, s, off);
        if (lane == 0) {
            s = s * g1s[o] + g1sh[o];
            t1[o] = s / (1.f + __expf(-s));
        }
    }
    __syncthreads();

    // stage 4: gate = sigmoid(cbn(wg2 @ t1))
    float gate;
    {
        const float4* wr = (const float4*)(wg2 + t * 64);
        float s = 0.f;
        #pragma unroll
        for (int c4 = 0; c4 < 16; ++c4) {
            float4 wv = wr[c4];
            s += wv.x * t1[c4 * 4 + 0] + wv.y * t1[c4 * 4 + 1]
               + wv.z * t1[c4 * 4 + 2] + wv.w * t1[c4 * 4 + 3];
        }
        s = s * g2s[t] + g2sh[t];
        gate = 1.f / (1.f + __expf(-s));
    }

    // ---------------- phase E: this axis' P or Q row for o = t ----------------
    int o = t;
    float scale = fs[o] * gate * 0.1f;
    float bias  = axis ? 0.f : fsh[o] * gate * 0.1f;
    float w[16];
    const float* wff = (const float*)wf;
    if (axis == 0) {
        #pragma unroll
        for (int c = 0; c < 16; ++c) w[c] = wff[c];
    } else {
        #pragma unroll
        for (int c = 0; c < 16; ++c) w[c] = wff[16 + c];
    }
    float* dst = (axis ? g_Q : g_P) + (b * 256 + o) * 64;
    const float4* base = (const float4*)sM;        // sM == this axis' attention

    #pragma unroll
    for (int lg = 0; lg < 16; ++lg) {
        float4 acc2 = {0.f, 0.f, 0.f, 0.f};
        #pragma unroll
        for (int c = 0; c < 16; ++c) {
            float4 xv = base[c * 16 + lg];     // warp-uniform broadcast
            acc2.x += w[c] * xv.x; acc2.y += w[c] * xv.y;
            acc2.z += w[c] * xv.z; acc2.w += w[c] * xv.w;
        }
        float4 r;
        r.x = acc2.x * scale + bias; r.y = acc2.y * scale + bias;
        r.z = acc2.z * scale + bias; r.w = acc2.w * scale + bias;
        ((float4*)dst)[lg] = r;
    }
}

// ---------------------------------------------------------------------------
// K6: out[b,o,h,w] = x + P[b,o,h] + Q[b,o,w].  8192 blocks, 256 threads.
// (R12 form — pinned: reversed tile order + __stcs stores only.)
// ---------------------------------------------------------------------------
__global__ void k6_final(const float* __restrict__ x, float* __restrict__ out) {
    int blk = 8191 - blockIdx.x;       // reverse: b*256+o from the tail
    __shared__ float  sp[64];
    __shared__ float4 sq4[16];
    int t = threadIdx.x;
    if (t < 64) sp[t] = g_P[blk * 64 + t];
    else if (t < 80) sq4[t - 64] = ((const float4*)(g_Q + blk * 64))[t - 64];
    __syncthreads();

    const float4* xi = (const float4*)(x + (size_t)blk * 4096);
    float4*       xo = (float4*)(out + (size_t)blk * 4096);
    #pragma unroll
    for (int i = 0; i < 4; ++i) {
        int j = t + 256 * i;
        float  p  = sp[j >> 4];
        float4 qv = sq4[j & 15];
        float4 xv = xi[j];
        float4 r;
        r.x = xv.x + p + qv.x;
        r.y = xv.y + p + qv.y;
        r.z = xv.z + p + qv.z;
        r.w = xv.w + p + qv.w;
        __stcs(xo + j, r);
    }
}

// ---------------------------------------------------------------------------
// Input identification by element count (robust to metadata ordering).
// ---------------------------------------------------------------------------
extern "C" void kernel_launch(void* const* d_in, const int* in_sizes, int n_in,
                              void* d_out, int out_size) {
    const float *x = 0, *w_qkv = 0, *qkv_scale = 0, *qkv_shift = 0;
    const float *pos_h = 0, *pos_w = 0, *w_fusion = 0;
    const float *fusion_scale = 0, *fusion_shift = 0;
    const float *w_g1 = 0, *g1_scale = 0, *g1_shift = 0;
    const float *w_g2 = 0, *g2_scale = 0, *g2_shift = 0;

    int n48 = 0, n64 = 0, n256 = 0, n1024 = 0, n16384 = 0;
    for (int i = 0; i < n_in; ++i) {
        const float* p = (const float*)d_in[i];
        switch (in_sizes[i]) {
            case 33554432: x = p; break;
            case 12288:    w_qkv = p; break;
            case 8192:     w_fusion = p; break;
            case 48:
                if (n48++ == 0) qkv_scale = p; else qkv_shift = p; break;
            case 1024:
                if (n1024++ == 0) pos_h = p; else pos_w = p; break;
            case 16384:
                if (n16384++ == 0) w_g1 = p; else w_g2 = p; break;
            case 64:
                if (n64++ == 0) g1_scale = p; else g1_shift = p; break;
            case 256:
                switch (n256++) {
                    case 0: fusion_scale = p; break;
                    case 1: fusion_shift = p; break;
                    case 2: g2_scale = p; break;
                    default: g2_shift = p; break;
                }
                break;
            default: break;
        }
    }
    float* out = (float*)d_out;

    k1_reduce<<<BB * CC, 256>>>(x);
    k2345_fused<<<64, 256>>>(w_qkv, qkv_scale, qkv_shift, pos_h, pos_w,
                             w_fusion, fusion_scale, fusion_shift,
                             w_g1, g1_scale, g1_shift,
                             w_g2, g2_scale, g2_shift);
    k6_final<<<BB * CC, 256>>>(x, out);
}